// round 6
// baseline (speedup 1.0000x reference)
#include <cuda_runtime.h>
#include <cstdint>

typedef unsigned long long ull;

#define KOUT     16
#define NOUT     262144        // 64*512*8
#define TILE_R   8
#define NTILES   4096          // 32768 rows / 8
#define GRID     152
#define NTHR     512
#define BATCH    4

// ---- shared memory layout (bytes) ----
#define STAGE_BYTES 32768                  // 8 rows * 4096B, swizzled
#define XS_OFF      0
#define RED_OFF     (2*STAGE_BYTES)        // 65536
#define RED_FLOATS  (BATCH*16*128)         // tile x warp x (row*16+k) = 8192
#define BIAS_OFF    (RED_OFF + RED_FLOATS*4)   // 98304
#define PART_OFF    (BIAS_OFF + 64)            // 98368
#define SMEM_TOTAL  (PART_OFF + 192)           // 98560

__device__ float        g_nll;
__device__ int          g_cnt;
__device__ unsigned int g_ticket;

__device__ __forceinline__ ull fma2(ull a, ull b, ull c) {
    ull d;
    asm("fma.rn.f32x2 %0, %1, %2, %3;" : "=l"(d) : "l"(a), "l"(b), "l"(c));
    return d;
}
__device__ __forceinline__ ull add2(ull a, ull b) {
    ull d;
    asm("add.rn.f32x2 %0, %1, %2;" : "=l"(d) : "l"(a), "l"(b));
    return d;
}
__device__ __forceinline__ float lo32(ull v) { return __uint_as_float((unsigned)(v & 0xffffffffu)); }
__device__ __forceinline__ float hi32(ull v) { return __uint_as_float((unsigned)(v >> 32)); }
__device__ __forceinline__ ull pack2(float lo, float hi) {
    return ((ull)__float_as_uint(hi) << 32) | (ull)__float_as_uint(lo);
}

__device__ __forceinline__ void cp16(uint32_t s, const void* g) {
    asm volatile("cp.async.cg.shared.global [%0], [%1], 16;" :: "r"(s), "l"(g) : "memory");
}
#define CP_COMMIT() asm volatile("cp.async.commit_group;" ::: "memory")
#define CP_WAIT0()  asm volatile("cp.async.wait_group 0;" ::: "memory")

// 16B-chunk index swizzle within a 4KB row (128B XOR swizzle)
__device__ __forceinline__ uint32_t swz(uint32_t u) { return u ^ ((u >> 3) & 7u); }

__device__ __forceinline__ void issue_tile_load(const float* __restrict__ X,
                                                uint32_t smem_base, int tile,
                                                int stg, int tid) {
    const char* g = (const char*)X + (size_t)tile * STAGE_BYTES;
    uint32_t sb = smem_base + XS_OFF + (uint32_t)stg * STAGE_BYTES;
    #pragma unroll
    for (int i = 0; i < 4; i++) {                 // 512 thr * 4 * 16B = 32KB
        int c   = tid + i * NTHR;                 // 16B chunk 0..2047
        int row = c >> 8;
        uint32_t u = (uint32_t)(c & 255);
        cp16(sb + (uint32_t)row * 4096u + swz(u) * 16u, g + (size_t)c * 16);
    }
    CP_COMMIT();
}

__global__ __launch_bounds__(NTHR, 1)
void rpn_fused_kernel(const float* __restrict__ X,
                      const float* __restrict__ W,
                      const float* __restrict__ bvec,
                      const int*   __restrict__ labels,
                      float* __restrict__ out)
{
    extern __shared__ char smem[];
    float* red    = (float*)(smem + RED_OFF);
    float* bias_s = (float*)(smem + BIAS_OFF);
    float* pn     = (float*)(smem + PART_OFF);
    int*   pc     = (int*)(smem + PART_OFF + 64);

    const int tid  = threadIdx.x;
    const int w    = tid >> 5;          // warp 0..15
    const int lane = tid & 31;
    const int kh   = lane & 7;          // k-group: k = kh*2 + {0,1}
    const int j    = lane >> 3;         // pair-group within warp (0..3)
    const int pg   = w * 4 + j;         // global pair-group 0..63

    const uint32_t smem_base = (uint32_t)__cvta_generic_to_shared(smem);
    const int bid = blockIdx.x;
    const int cnt = (NTILES - bid + GRID - 1) / GRID;   // tiles for this CTA (>=26)

    // Prologue: first tile load in flight before anything else
    issue_tile_load(X, smem_base, bid, 0, tid);

    // W slice -> registers (once): wreg[pp][kk] = (W[2p][k], W[2p+1][k])
    ull wreg[8][2];
    #pragma unroll
    for (int pp = 0; pp < 8; pp++) {
        int p = pg * 8 + pp;
        #pragma unroll
        for (int kk = 0; kk < 2; kk++) {
            int k = kh * 2 + kk;
            wreg[pp][kk] = pack2(__ldg(&W[p * 32 + k]), __ldg(&W[p * 32 + 16 + k]));
        }
    }
    if (tid < KOUT) bias_s[tid] = bvec[tid];

    float run_nll = 0.0f;
    int   run_cnt = 0;

    int i = 0, stg = 0;
    while (i < cnt) {
        const int nb = (cnt - i < BATCH) ? (cnt - i) : BATCH;
        const int ibase = i;

        for (int tm = 0; tm < nb; tm++, i++, stg ^= 1) {
            CP_WAIT0();
            __syncthreads();            // load(i) visible; stage stg^1 reads done
            if (i + 1 < cnt)
                issue_tile_load(X, smem_base, bid + (i + 1) * GRID, stg ^ 1, tid);

            const char* xb = smem + XS_OFF + stg * STAGE_BYTES;

            ull acc[TILE_R][2];
            #pragma unroll
            for (int r = 0; r < TILE_R; r++) { acc[r][0] = 0ULL; acc[r][1] = 0ULL; }

            #pragma unroll
            for (int it = 0; it < 4; it++) {
                uint32_t off = swz((uint32_t)(pg * 4 + it)) * 16u;
                ulonglong2 xv[TILE_R];
                #pragma unroll
                for (int r = 0; r < TILE_R; r++)
                    xv[r] = *(const ulonglong2*)(xb + r * 4096 + off);
                #pragma unroll
                for (int r = 0; r < TILE_R; r++) {
                    #pragma unroll
                    for (int kk = 0; kk < 2; kk++) {
                        acc[r][kk] = fma2(xv[r].x, wreg[it * 2][kk],     acc[r][kk]);
                        acc[r][kk] = fma2(xv[r].y, wreg[it * 2 + 1][kk], acc[r][kk]);
                    }
                }
            }

            // Reduce over the 4 pair-groups within the warp (lane bits 3,4)
            #pragma unroll
            for (int r = 0; r < TILE_R; r++) {
                #pragma unroll
                for (int kk = 0; kk < 2; kk++) {
                    ull v = acc[r][kk];
                    v = add2(v, __shfl_xor_sync(0xffffffffu, v, 8));
                    v = add2(v, __shfl_xor_sync(0xffffffffu, v, 16));
                    acc[r][kk] = v;
                }
            }
            if (j == 0) {   // lanes 0..7: collapse pair halves, store float2 per (r, 2kh)
                float* rp = red + (tm * 16 + w) * 128;
                #pragma unroll
                for (int r = 0; r < TILE_R; r++) {
                    float2 v;
                    v.x = lo32(acc[r][0]) + hi32(acc[r][0]);
                    v.y = lo32(acc[r][1]) + hi32(acc[r][1]);
                    *(float2*)&rp[r * 16 + kh * 2] = v;
                }
            }
        }

        __syncthreads();    // all red writes for this batch visible

        // Full-width reduce + epilogue: thread = (tm, row, k)
        {
            const int tm  = tid >> 7;
            const int row = (tid >> 4) & 7;
            const int k   = tid & 15;
            const float* rp = red + tm * 16 * 128 + row * 16 + k;
            float s0 = 0.f, s1 = 0.f, s2 = 0.f, s3 = 0.f;
            #pragma unroll
            for (int ww = 0; ww < 16; ww += 4) {
                s0 += rp[(ww + 0) * 128];
                s1 += rp[(ww + 1) * 128];
                s2 += rp[(ww + 2) * 128];
                s3 += rp[(ww + 3) * 128];
            }
            float logit = (s0 + s1) + (s2 + s3) + bias_s[k];
            float lnext = __shfl_down_sync(0xffffffffu, logit, 1);

            if (tm < nb && (k & 1) == 0) {
                float l0 = logit, l1 = lnext;
                int   a  = k >> 1;
                int   t  = bid + (ibase + tm) * GRID;
                int gidx = t * 64 + row * 8 + a;
                int lb = __ldg(&labels[gidx]);
                bool valid = (lb != -1);
                int  pred  = (l1 > l0) ? 1 : 0;
                float chosen = (lb == 1) ? l1 : l0;
                float other  = (lb == 1) ? l0 : l1;
                float d = other - chosen;
                float nll = (d > 0.0f) ? (d + log1pf(expf(-d))) : log1pf(expf(d));
                if (valid) { run_nll += nll; run_cnt++; }
                out[1 + gidx]        = (float)pred;
                out[1 + NOUT + gidx] = (pred == 1 && valid) ? 1.0f : 0.0f;
            }
        }
        __syncthreads();    // red reads done before next batch rewrites it
    }

    // ---- loss: warp -> CTA -> chip (last-CTA ticket) ----
    #pragma unroll
    for (int off = 16; off > 0; off >>= 1) {
        run_nll += __shfl_down_sync(0xffffffffu, run_nll, off);
        run_cnt += __shfl_down_sync(0xffffffffu, run_cnt, off);
    }
    if (lane == 0) { pn[w] = run_nll; pc[w] = run_cnt; }
    __syncthreads();
    if (tid == 0) {
        float s = 0.0f; int c = 0;
        #pragma unroll
        for (int ww = 0; ww < 16; ww++) { s += pn[ww]; c += pc[ww]; }
        atomicAdd(&g_nll, s);
        atomicAdd(&g_cnt, c);
        __threadfence();
        unsigned tk = atomicAdd(&g_ticket, 1u);
        if (tk == GRID - 1) {
            float tot  = atomicAdd(&g_nll, 0.0f);
            int   totc = atomicAdd(&g_cnt, 0);
            out[0] = tot / fmaxf((float)totc, 1.0f);
            g_nll = 0.0f; g_cnt = 0; g_ticket = 0u;   // reset for graph replay
        }
    }
}

extern "C" void kernel_launch(void* const* d_in, const int* in_sizes, int n_in,
                              void* d_out, int out_size)
{
    const float* X = nullptr;
    const float* W = nullptr;
    const float* b = nullptr;
    const int* labels = nullptr;
    for (int i = 0; i < n_in; i++) {
        switch (in_sizes[i]) {
            case 33554432: X = (const float*)d_in[i]; break;       // 64*512*1024
            case 16384:    W = (const float*)d_in[i]; break;       // 1024*16
            case KOUT:     b = (const float*)d_in[i]; break;       // 16
            case NOUT:     labels = (const int*)d_in[i]; break;    // 64*512*8
            default: break;
        }
    }
    float* out = (float*)d_out;

    static bool attr_set = false;  // idempotent host-side attribute (no device work)
    if (!attr_set) {
        cudaFuncSetAttribute(rpn_fused_kernel,
                             cudaFuncAttributeMaxDynamicSharedMemorySize, SMEM_TOTAL);
        attr_set = true;
    }

    rpn_fused_kernel<<<GRID, NTHR, SMEM_TOTAL>>>(X, W, b, labels, out);
}

// round 9
// speedup vs baseline: 1.1986x; 1.1986x over previous
#include <cuda_runtime.h>
#include <cstdint>

typedef unsigned long long ull;

#define KOUT     16
#define NOUT     262144        // 64*512*8
#define TILE_R   16
#define NTILES   2048          // 32768 rows / 16
#define GRID     152
#define NTHR     512

// ---- shared memory layout (bytes) ----
#define STAGE_BYTES 65536                  // 16 rows * 4096B, swizzled
#define XS_OFF      0
#define RED_OFF     (2*STAGE_BYTES)        // 131072
#define RED_FLOATS  (16*128)               // warp x (row*16+k), one 8-row half
#define BIAS_OFF    (RED_OFF + RED_FLOATS*4)   // 139264
#define PART_OFF    (BIAS_OFF + 64)
#define SMEM_TOTAL  (PART_OFF + 192)           // ~139.6KB

__device__ float        g_nll;
__device__ int          g_cnt;
__device__ unsigned int g_ticket;

__device__ __forceinline__ ull fma2(ull a, ull b, ull c) {
    ull d;
    asm("fma.rn.f32x2 %0, %1, %2, %3;" : "=l"(d) : "l"(a), "l"(b), "l"(c));
    return d;
}
__device__ __forceinline__ ull add2(ull a, ull b) {
    ull d;
    asm("add.rn.f32x2 %0, %1, %2;" : "=l"(d) : "l"(a), "l"(b));
    return d;
}
__device__ __forceinline__ float lo32(ull v) { return __uint_as_float((unsigned)(v & 0xffffffffu)); }
__device__ __forceinline__ float hi32(ull v) { return __uint_as_float((unsigned)(v >> 32)); }
__device__ __forceinline__ ull pack2(float lo, float hi) {
    return ((ull)__float_as_uint(hi) << 32) | (ull)__float_as_uint(lo);
}

__device__ __forceinline__ void cp16(uint32_t s, const void* g) {
    asm volatile("cp.async.cg.shared.global [%0], [%1], 16;" :: "r"(s), "l"(g) : "memory");
}
#define CP_COMMIT() asm volatile("cp.async.commit_group;" ::: "memory")
#define CP_WAIT1()  asm volatile("cp.async.wait_group 1;" ::: "memory")
#define CP_WAIT0()  asm volatile("cp.async.wait_group 0;" ::: "memory")

// 16B-chunk index swizzle within a 4KB row (128B XOR swizzle)
__device__ __forceinline__ uint32_t swz(uint32_t u) { return u ^ ((u >> 3) & 7u); }

__device__ __forceinline__ void issue_tile_load(const float* __restrict__ X,
                                                uint32_t smem_base, int tile,
                                                int stg, int tid) {
    const char* g = (const char*)X + (size_t)tile * STAGE_BYTES;
    uint32_t sb = smem_base + XS_OFF + (uint32_t)stg * STAGE_BYTES;
    #pragma unroll
    for (int i = 0; i < 8; i++) {                 // 512 thr * 8 * 16B = 64KB
        int c   = tid + i * NTHR;                 // 16B chunk 0..4095
        int row = c >> 8;
        uint32_t u = (uint32_t)(c & 255);
        cp16(sb + (uint32_t)row * 4096u + swz(u) * 16u, g + (size_t)c * 16);
    }
    CP_COMMIT();
}

__global__ __launch_bounds__(NTHR, 1)
void rpn_fused_kernel(const float* __restrict__ X,
                      const float* __restrict__ W,
                      const float* __restrict__ bvec,
                      const int*   __restrict__ labels,
                      float* __restrict__ out)
{
    extern __shared__ char smem[];
    float* red    = (float*)(smem + RED_OFF);
    float* bias_s = (float*)(smem + BIAS_OFF);
    float* pn     = (float*)(smem + PART_OFF);
    int*   pc     = (int*)(smem + PART_OFF + 64);

    const int tid  = threadIdx.x;
    const int w    = tid >> 5;          // warp 0..15
    const int lane = tid & 31;
    const int kh   = lane & 7;          // k-group: k = kh*2 + {0,1}
    const int j    = lane >> 3;         // pair-group within warp (0..3)
    const int pg   = w * 4 + j;         // global pair-group 0..63

    const uint32_t smem_base = (uint32_t)__cvta_generic_to_shared(smem);
    const int bid = blockIdx.x;
    const int cnt = (NTILES - bid + GRID - 1) / GRID;   // 13 or 14 tiles

    // Prologue: first tile load in flight before anything else
    issue_tile_load(X, smem_base, bid, 0, tid);

    // W slice -> registers (once): wreg[pp][kk] = (W[2p][k], W[2p+1][k])
    ull wreg[8][2];
    #pragma unroll
    for (int pp = 0; pp < 8; pp++) {
        int p = pg * 8 + pp;
        #pragma unroll
        for (int kk = 0; kk < 2; kk++) {
            int k = kh * 2 + kk;
            wreg[pp][kk] = pack2(__ldg(&W[p * 32 + k]), __ldg(&W[p * 32 + 16 + k]));
        }
    }
    if (tid < KOUT) bias_s[tid] = bvec[tid];

    float run_nll = 0.0f;
    int   run_cnt = 0;

    int stg = 0;
    for (int i = 0; i < cnt; i++, stg ^= 1) {
        const int t = bid + i * GRID;
        // R3-order pipeline: issue next load first, then wait for current.
        // Stage stg^1's readers all finished before the last sync of iter i-1.
        if (i + 1 < cnt) {
            issue_tile_load(X, smem_base, bid + (i + 1) * GRID, stg ^ 1, tid);
            CP_WAIT1();
        } else {
            CP_WAIT0();
        }
        __syncthreads();                 // load(i) visible to all

        const char* xs = smem + XS_OFF + stg * STAGE_BYTES;

        #pragma unroll
        for (int h = 0; h < 2; h++) {    // two 8-row halves reuse acc/xv regs
            const char* xb = xs + h * 8 * 4096;

            ull acc[8][2];
            #pragma unroll
            for (int r = 0; r < 8; r++) { acc[r][0] = 0ULL; acc[r][1] = 0ULL; }

            #pragma unroll
            for (int it = 0; it < 4; it++) {
                uint32_t off = swz((uint32_t)(pg * 4 + it)) * 16u;
                ulonglong2 xv[8];
                #pragma unroll
                for (int r = 0; r < 8; r++)
                    xv[r] = *(const ulonglong2*)(xb + r * 4096 + off);
                #pragma unroll
                for (int r = 0; r < 8; r++) {
                    #pragma unroll
                    for (int kk = 0; kk < 2; kk++) {
                        acc[r][kk] = fma2(xv[r].x, wreg[it * 2][kk],     acc[r][kk]);
                        acc[r][kk] = fma2(xv[r].y, wreg[it * 2 + 1][kk], acc[r][kk]);
                    }
                }
            }

            // Reduce over the 4 pair-groups within the warp (lane bits 3,4)
            #pragma unroll
            for (int r = 0; r < 8; r++) {
                #pragma unroll
                for (int kk = 0; kk < 2; kk++) {
                    ull v = acc[r][kk];
                    v = add2(v, __shfl_xor_sync(0xffffffffu, v, 8));
                    v = add2(v, __shfl_xor_sync(0xffffffffu, v, 16));
                    acc[r][kk] = v;
                }
            }
            if (j == 0) {   // lanes 0..7: collapse col-pair halves, store per (r, 2kh)
                float* rp = red + w * 128;
                #pragma unroll
                for (int r = 0; r < 8; r++) {
                    float2 v;
                    v.x = lo32(acc[r][0]) + hi32(acc[r][0]);
                    v.y = lo32(acc[r][1]) + hi32(acc[r][1]);
                    *(float2*)&rp[r * 16 + kh * 2] = v;
                }
            }
            __syncthreads();     // red writes visible

            // Fused cross-warp reduce + logits + epilogue: 128 threads = (row, k)
            if (tid < 128) {
                const int row = tid >> 4, k = tid & 15;
                const float* rp = red + row * 16 + k;
                float s0 = 0.f, s1 = 0.f, s2 = 0.f, s3 = 0.f;
                #pragma unroll
                for (int ww = 0; ww < 16; ww += 4) {
                    s0 += rp[(ww + 0) * 128];
                    s1 += rp[(ww + 1) * 128];
                    s2 += rp[(ww + 2) * 128];
                    s3 += rp[(ww + 3) * 128];
                }
                float logit = (s0 + s1) + (s2 + s3) + bias_s[k];
                float lnext = __shfl_down_sync(0xffffffffu, logit, 1);

                if ((k & 1) == 0) {
                    float l0 = logit, l1 = lnext;
                    int   a  = k >> 1;
                    int gidx = t * 128 + h * 64 + row * 8 + a;
                    int lb = __ldg(&labels[gidx]);
                    bool valid = (lb != -1);
                    int  pred  = (l1 > l0) ? 1 : 0;
                    float chosen = (lb == 1) ? l1 : l0;
                    float other  = (lb == 1) ? l0 : l1;
                    float d = other - chosen;
                    float nll = (d > 0.0f) ? (d + log1pf(expf(-d))) : log1pf(expf(d));
                    if (valid) { run_nll += nll; run_cnt++; }
                    out[1 + gidx]        = (float)pred;
                    out[1 + NOUT + gidx] = (pred == 1 && valid) ? 1.0f : 0.0f;
                }
            }
            __syncthreads();     // red reads done before next half rewrites
        }
    }

    // ---- loss: warp -> CTA -> chip (last-CTA ticket) ----
    #pragma unroll
    for (int off = 16; off > 0; off >>= 1) {
        run_nll += __shfl_down_sync(0xffffffffu, run_nll, off);
        run_cnt += __shfl_down_sync(0xffffffffu, run_cnt, off);
    }
    if (lane == 0) { pn[w] = run_nll; pc[w] = run_cnt; }
    __syncthreads();
    if (tid == 0) {
        float s = 0.0f; int c = 0;
        #pragma unroll
        for (int ww = 0; ww < 16; ww++) { s += pn[ww]; c += pc[ww]; }
        atomicAdd(&g_nll, s);
        atomicAdd(&g_cnt, c);
        __threadfence();
        unsigned tk = atomicAdd(&g_ticket, 1u);
        if (tk == GRID - 1) {
            float tot  = atomicAdd(&g_nll, 0.0f);
            int   totc = atomicAdd(&g_cnt, 0);
            out[0] = tot / fmaxf((float)totc, 1.0f);
            g_nll = 0.0f; g_cnt = 0; g_ticket = 0u;   // reset for graph replay
        }
    }
}

extern "C" void kernel_launch(void* const* d_in, const int* in_sizes, int n_in,
                              void* d_out, int out_size)
{
    const float* X = nullptr;
    const float* W = nullptr;
    const float* b = nullptr;
    const int* labels = nullptr;
    for (int i = 0; i < n_in; i++) {
        switch (in_sizes[i]) {
            case 33554432: X = (const float*)d_in[i]; break;       // 64*512*1024
            case 16384:    W = (const float*)d_in[i]; break;       // 1024*16
            case KOUT:     b = (const float*)d_in[i]; break;       // 16
            case NOUT:     labels = (const int*)d_in[i]; break;    // 64*512*8
            default: break;
        }
    }
    float* out = (float*)d_out;

    static bool attr_set = false;  // idempotent host-side attribute (no device work)
    if (!attr_set) {
        cudaFuncSetAttribute(rpn_fused_kernel,
                             cudaFuncAttributeMaxDynamicSharedMemorySize, SMEM_TOTAL);
        attr_set = true;
    }

    rpn_fused_kernel<<<GRID, NTHR, SMEM_TOTAL>>>(X, W, b, labels, out);
}